// round 1
// baseline (speedup 1.0000x reference)
#include <cuda_runtime.h>
#include <cuda_bf16.h>
#include <cstdint>

// ---------------------------------------------------------------------------
// GatedShortBlock:
//   BCx = x @ w1^T            (M=16384, N=6144, K=2048)
//   Bg, Cg, Xg = split(BCx)
//   u  = Cg * causal_depthwise_conv4(Bg * Xg)
//   out = u @ w2^T            (M=16384, N=2048, K=2048)
// ---------------------------------------------------------------------------

#define D_MODEL 2048
#define SEQ     4096
#define BATCH   4
#define MTOK    (BATCH * SEQ)        // 16384
#define N1      (3 * D_MODEL)        // 6144
#define KSZ     4

// Scratch (allocation-free rule: __device__ globals)
__device__ float g_bcx[(size_t)MTOK * N1];      // 402 MB
__device__ float g_u[(size_t)MTOK * D_MODEL];   // 134 MB

// ---------------------------------------------------------------------------
// SGEMM: C[M,N] = A[M,K] * B[N,K]^T   (A, B row-major, K contiguous)
// Block tile 128x128, K-tile 16, 256 threads, 8x8 per-thread tile.
// M, N, K all multiples of tile sizes for this problem -> no bounds checks.
// ---------------------------------------------------------------------------
#define BM 128
#define BN 128
#define BK 16
#define TM 8
#define TN 8

__global__ __launch_bounds__(256, 2) void sgemm_abt(
    const float* __restrict__ A, const float* __restrict__ B,
    float* __restrict__ C, int M, int N, int K)
{
    __shared__ float As[BK][BM];
    __shared__ float Bs[BK][BN];

    const int tid = threadIdx.x;
    const int tx = tid & 15;   // 0..15 -> N direction
    const int ty = tid >> 4;   // 0..15 -> M direction

    const size_t m0 = (size_t)blockIdx.y * BM;
    const size_t n0 = (size_t)blockIdx.x * BN;

    const float* Ab = A + m0 * (size_t)K;
    const float* Bb = B + n0 * (size_t)K;

    float acc[TM][TN];
    #pragma unroll
    for (int i = 0; i < TM; i++)
        #pragma unroll
        for (int j = 0; j < TN; j++)
            acc[i][j] = 0.0f;

    for (int k0 = 0; k0 < K; k0 += BK) {
        // Load 128x16 A tile and 128x16 B tile, transposed into smem.
        // 512 float4 per tile, 256 threads -> 2 float4 each.
        #pragma unroll
        for (int l = 0; l < 2; l++) {
            int idx = tid + l * 256;
            int row = idx >> 2;       // 0..127
            int c4  = idx & 3;        // which float4 within the 16-wide K slab
            float4 va = *reinterpret_cast<const float4*>(
                Ab + (size_t)row * K + k0 + c4 * 4);
            As[c4 * 4 + 0][row] = va.x;
            As[c4 * 4 + 1][row] = va.y;
            As[c4 * 4 + 2][row] = va.z;
            As[c4 * 4 + 3][row] = va.w;
            float4 vb = *reinterpret_cast<const float4*>(
                Bb + (size_t)row * K + k0 + c4 * 4);
            Bs[c4 * 4 + 0][row] = vb.x;
            Bs[c4 * 4 + 1][row] = vb.y;
            Bs[c4 * 4 + 2][row] = vb.z;
            Bs[c4 * 4 + 3][row] = vb.w;
        }
        __syncthreads();

        #pragma unroll
        for (int kk = 0; kk < BK; kk++) {
            float a[TM], b[TN];
            *reinterpret_cast<float4*>(a)     = *reinterpret_cast<const float4*>(&As[kk][ty * TM]);
            *reinterpret_cast<float4*>(a + 4) = *reinterpret_cast<const float4*>(&As[kk][ty * TM + 4]);
            *reinterpret_cast<float4*>(b)     = *reinterpret_cast<const float4*>(&Bs[kk][tx * TN]);
            *reinterpret_cast<float4*>(b + 4) = *reinterpret_cast<const float4*>(&Bs[kk][tx * TN + 4]);
            #pragma unroll
            for (int i = 0; i < TM; i++)
                #pragma unroll
                for (int j = 0; j < TN; j++)
                    acc[i][j] = fmaf(a[i], b[j], acc[i][j]);
        }
        __syncthreads();
    }

    // Write back
    #pragma unroll
    for (int i = 0; i < TM; i++) {
        size_t row = m0 + ty * TM + i;
        float* Cp = C + row * (size_t)N + n0 + tx * TN;
        #pragma unroll
        for (int j = 0; j < TN; j += 4) {
            float4 v = make_float4(acc[i][j], acc[i][j + 1], acc[i][j + 2], acc[i][j + 3]);
            *reinterpret_cast<float4*>(Cp + j) = v;
        }
    }
}

// ---------------------------------------------------------------------------
// Fused gate + depthwise causal conv (K=4) + second gate:
//   gated[t,d]  = BCx[t,d] * BCx[t, 2D+d]
//   conv[t,d]   = sum_{k=0..3} gated[t-3+k, d] * cw[d,k]   (zeros before seq start)
//   u[t,d]      = BCx[t, D+d] * conv[t,d]
// One thread per (m, d); d is the fast (coalesced) dimension.
// ---------------------------------------------------------------------------
__global__ __launch_bounds__(256) void conv_gate_kernel(
    const float* __restrict__ bcx, const float* __restrict__ cw,
    float* __restrict__ u)
{
    size_t idx = (size_t)blockIdx.x * blockDim.x + threadIdx.x;
    if (idx >= (size_t)MTOK * D_MODEL) return;
    int d = (int)(idx % D_MODEL);
    size_t m = idx / D_MODEL;
    int s = (int)(m % SEQ);   // position within the sequence (causality boundary)

    float w0 = cw[d * KSZ + 0];
    float w1 = cw[d * KSZ + 1];
    float w2 = cw[d * KSZ + 2];
    float w3 = cw[d * KSZ + 3];

    float accum = 0.0f;
    // tap k contributes gated[m - (3-k)] * w[k]
    #pragma unroll
    for (int k = 0; k < KSZ; k++) {
        int back = (KSZ - 1) - k;   // 3,2,1,0
        if (s - back >= 0) {
            size_t mp = m - back;
            const float* row = bcx + mp * (size_t)N1;
            float g = row[d] * row[2 * D_MODEL + d];
            float wk = (k == 0) ? w0 : (k == 1) ? w1 : (k == 2) ? w2 : w3;
            accum = fmaf(g, wk, accum);
        }
    }
    float cg = bcx[m * (size_t)N1 + D_MODEL + d];
    u[idx] = cg * accum;
}

// ---------------------------------------------------------------------------
// Launcher
// inputs (metadata order): x [4,4096,2048] f32, w1 [6144,2048] f32,
//                          w2 [2048,2048] f32, conv_w [2048,1,4] f32
// output: [4,4096,2048] f32
// ---------------------------------------------------------------------------
extern "C" void kernel_launch(void* const* d_in, const int* in_sizes, int n_in,
                              void* d_out, int out_size)
{
    const float* x  = (const float*)d_in[0];
    const float* w1 = (const float*)d_in[1];
    const float* w2 = (const float*)d_in[2];
    const float* cw = (const float*)d_in[3];
    float* out = (float*)d_out;

    float* bcx = nullptr;
    float* u   = nullptr;
    cudaGetSymbolAddress((void**)&bcx, g_bcx);
    cudaGetSymbolAddress((void**)&u,   g_u);

    // GEMM1: BCx = x @ w1^T   (M=16384, N=6144, K=2048)
    {
        dim3 grid(N1 / BN, MTOK / BM);
        sgemm_abt<<<grid, 256>>>(x, w1, bcx, MTOK, N1, D_MODEL);
    }

    // Fused gate + causal depthwise conv + gate
    {
        size_t total = (size_t)MTOK * D_MODEL;
        int threads = 256;
        int blocks = (int)((total + threads - 1) / threads);
        conv_gate_kernel<<<blocks, threads>>>(bcx, cw, u);
    }

    // GEMM2: out = u @ w2^T   (M=16384, N=2048, K=2048)
    {
        dim3 grid(D_MODEL / BN, MTOK / BM);
        sgemm_abt<<<grid, 256>>>(u, w2, out, MTOK, D_MODEL, D_MODEL);
    }
}

// round 3
// speedup vs baseline: 2.4309x; 2.4309x over previous
#include <cuda_runtime.h>
#include <cuda_bf16.h>
#include <cstdint>

// ---------------------------------------------------------------------------
// GatedShortBlock via split-bf16 HMMA (mma.sync) GEMMs:
//   bcx = x @ w1^T        (16384 x 6144, K=2048)
//   u   = Cg * causal_conv4(Bg * Xg)
//   out = u @ w2^T        (16384 x 2048, K=2048)
// fp32 emulated as Ah*Bh + Ah*Bl + Al*Bh with bf16 operands, fp32 accum.
// (tcgen05 is rejected by the harness's .target sm_103 PTX; mma.sync is the
//  family-portable tensor path.)
// ---------------------------------------------------------------------------

#define D_MODEL 2048
#define SEQ     4096
#define MTOK    16384
#define N1      6144
#define KEL     2048
#define KT_STEPS 32          // 2048 / 64
#define KSZ     4

// ---------------- scratch ----------------------------------------------------
__device__ __align__(16) __nv_bfloat16 g_xh [(size_t)MTOK * KEL];
__device__ __align__(16) __nv_bfloat16 g_xl [(size_t)MTOK * KEL];
__device__ __align__(16) __nv_bfloat16 g_w1h[(size_t)N1 * KEL];
__device__ __align__(16) __nv_bfloat16 g_w1l[(size_t)N1 * KEL];
__device__ __align__(16) __nv_bfloat16 g_w2h[(size_t)D_MODEL * KEL];
__device__ __align__(16) __nv_bfloat16 g_w2l[(size_t)D_MODEL * KEL];
__device__ __align__(16) __nv_bfloat16 g_uh [(size_t)MTOK * KEL];
__device__ __align__(16) __nv_bfloat16 g_ul [(size_t)MTOK * KEL];
__device__ float g_bcx[(size_t)MTOK * N1];

// ---------------- asm helpers ------------------------------------------------
__device__ __forceinline__ uint32_t smem_u32(const void* p) {
    uint32_t a;
    asm("{ .reg .u64 t; cvta.to.shared.u64 t, %1; cvt.u32.u64 %0, t; }" : "=r"(a) : "l"(p));
    return a;
}
__device__ __forceinline__ void cp16(uint32_t dst, const void* src) {
    asm volatile("cp.async.cg.shared.global [%0], [%1], 16;" :: "r"(dst), "l"(src));
}
#define CP_COMMIT() asm volatile("cp.async.commit_group;" ::: "memory")
#define CP_WAIT1()  asm volatile("cp.async.wait_group 1;" ::: "memory")

#define LDSM_X4(r0, r1, r2, r3, addr) \
    asm volatile("ldmatrix.sync.aligned.m8n8.x4.shared.b16 {%0,%1,%2,%3}, [%4];" \
        : "=r"(r0), "=r"(r1), "=r"(r2), "=r"(r3) : "r"(addr))

#define MMA16816(c, a, b) \
    asm volatile("mma.sync.aligned.m16n8k16.row.col.f32.bf16.bf16.f32 " \
        "{%0,%1,%2,%3}, {%4,%5,%6,%7}, {%8,%9}, {%0,%1,%2,%3};" \
        : "+f"((c)[0]), "+f"((c)[1]), "+f"((c)[2]), "+f"((c)[3]) \
        : "r"((a)[0]), "r"((a)[1]), "r"((a)[2]), "r"((a)[3]), \
          "r"((b)[0]), "r"((b)[1]))

// ---------------------------------------------------------------------------
// GEMM: C[M,N] = Ah*Bh^T + Ah*Bl^T + Al*Bh^T  (all K-major, K=2048)
// Tile 128x128, k-tile 64 (128B rows, XOR-swizzled smem), 256 threads,
// 3-stage cp.async pipeline. Warp grid 2(m) x 4(n), warp tile 64x32.
// ---------------------------------------------------------------------------
#define TILE_B    16384          // one 128x64 bf16 tile = 16KB
#define STAGE_B   (4 * TILE_B)   // Ah, Al, Bh, Bl
#define GEMM_SMEM (3 * STAGE_B)  // 196608

__global__ __launch_bounds__(256, 1) void gemm_split(
    const __nv_bfloat16* __restrict__ Ah, const __nv_bfloat16* __restrict__ Al,
    const __nv_bfloat16* __restrict__ Bh, const __nv_bfloat16* __restrict__ Bl,
    float* __restrict__ C, int Ntot)
{
    extern __shared__ __align__(1024) char smem[];
    const uint32_t sb = smem_u32(smem);
    const int tid  = threadIdx.x;
    const int lane = tid & 31;
    const int wid  = tid >> 5;
    const int wm   = wid >> 2;        // 0..1
    const int wn   = wid & 3;         // 0..3

    const size_t m0 = (size_t)blockIdx.y * 128;
    const size_t n0 = (size_t)blockIdx.x * 128;

    // ---- cp.async assignment: thread -> (row, 4 of 8 16B-chunks) -----------
    const int ldrow = tid >> 1;            // 0..127
    const int ldc0  = (tid & 1) * 4;       // 0 or 4
    const uint32_t swr = (uint32_t)(ldrow & 7);
    const char* gsrc[4];
    gsrc[0] = (const char*)(Ah + (m0 + ldrow) * (size_t)KEL);
    gsrc[1] = (const char*)(Al + (m0 + ldrow) * (size_t)KEL);
    gsrc[2] = (const char*)(Bh + (n0 + ldrow) * (size_t)KEL);
    gsrc[3] = (const char*)(Bl + (n0 + ldrow) * (size_t)KEL);
    uint32_t dbase[4];
    #pragma unroll
    for (int t = 0; t < 4; t++) dbase[t] = sb + t * TILE_B + ldrow * 128;

    auto load_stage = [&](int s, int kt) {
        #pragma unroll
        for (int t = 0; t < 4; t++) {
            const char* sp = gsrc[t] + kt * 128 + ldc0 * 16;
            const uint32_t db = dbase[t] + s * STAGE_B;
            #pragma unroll
            for (int q = 0; q < 4; q++)
                cp16(db + ((((uint32_t)(ldc0 + q)) ^ swr) << 4), sp + q * 16);
        }
    };

    load_stage(0, 0); CP_COMMIT();
    load_stage(1, 1); CP_COMMIT();

    float acc[4][4][4];
    #pragma unroll
    for (int i = 0; i < 4; i++)
        #pragma unroll
        for (int j = 0; j < 4; j++)
            #pragma unroll
            for (int q = 0; q < 4; q++) acc[i][j][q] = 0.0f;

    // ldmatrix lane address components
    const int lrow8  = lane & 7;
    const int lhalfA = (lane >> 3) & 1;   // +8 rows (A)
    const int lkA    = lane >> 4;         // +1 chunk (A)
    const int lhalfB = lane >> 4;         // +8 rows (B)
    const int lkB    = (lane >> 3) & 1;   // +1 chunk (B)

    for (int kt = 0; kt < KT_STEPS; kt++) {
        CP_WAIT1();
        __syncthreads();
        if (kt + 2 < KT_STEPS) load_stage((kt + 2) % 3, kt + 2);
        CP_COMMIT();

        const uint32_t st = sb + (kt % 3) * STAGE_B;
        #pragma unroll
        for (int ks = 0; ks < 4; ks++) {
            const int kc = ks * 2;
            uint32_t ahf[4][4], alf[4][4], bhf[4][2], blf[4][2];
            #pragma unroll
            for (int i = 0; i < 4; i++) {
                const int mrow = wm * 64 + i * 16 + lrow8 + lhalfA * 8;
                const uint32_t ad = st + mrow * 128 +
                    ((((uint32_t)(kc + lkA)) ^ (uint32_t)(mrow & 7)) << 4);
                LDSM_X4(ahf[i][0], ahf[i][1], ahf[i][2], ahf[i][3], ad);
                LDSM_X4(alf[i][0], alf[i][1], alf[i][2], alf[i][3], ad + TILE_B);
            }
            #pragma unroll
            for (int jp = 0; jp < 2; jp++) {
                const int nrow = wn * 32 + jp * 16 + lrow8 + lhalfB * 8;
                const uint32_t bd = st + 2 * TILE_B + nrow * 128 +
                    ((((uint32_t)(kc + lkB)) ^ (uint32_t)(nrow & 7)) << 4);
                uint32_t r0, r1, r2, r3;
                LDSM_X4(r0, r1, r2, r3, bd);
                bhf[jp * 2][0] = r0; bhf[jp * 2][1] = r1;
                bhf[jp * 2 + 1][0] = r2; bhf[jp * 2 + 1][1] = r3;
                LDSM_X4(r0, r1, r2, r3, bd + TILE_B);
                blf[jp * 2][0] = r0; blf[jp * 2][1] = r1;
                blf[jp * 2 + 1][0] = r2; blf[jp * 2 + 1][1] = r3;
            }
            #pragma unroll
            for (int i = 0; i < 4; i++)
                #pragma unroll
                for (int j = 0; j < 4; j++) {
                    MMA16816(acc[i][j], ahf[i], bhf[j]);
                    MMA16816(acc[i][j], ahf[i], blf[j]);
                    MMA16816(acc[i][j], alf[i], bhf[j]);
                }
        }
    }

    // ---- epilogue -----------------------------------------------------------
    #pragma unroll
    for (int i = 0; i < 4; i++) {
        const size_t r = m0 + wm * 64 + i * 16 + (lane >> 2);
        #pragma unroll
        for (int j = 0; j < 4; j++) {
            const size_t c = n0 + wn * 32 + j * 8 + (lane & 3) * 2;
            *reinterpret_cast<float2*>(C + r * (size_t)Ntot + c) =
                make_float2(acc[i][j][0], acc[i][j][1]);
            *reinterpret_cast<float2*>(C + (r + 8) * (size_t)Ntot + c) =
                make_float2(acc[i][j][2], acc[i][j][3]);
        }
    }
}

// ---------------------------------------------------------------------------
// fp32 -> (hi, lo) bf16 split, elementwise. 8 elements per thread.
// ---------------------------------------------------------------------------
__global__ __launch_bounds__(256) void split_bf16(
    const float* __restrict__ src, __nv_bfloat16* __restrict__ hi,
    __nv_bfloat16* __restrict__ lo, size_t total8)
{
    size_t idx = (size_t)blockIdx.x * blockDim.x + threadIdx.x;
    if (idx >= total8) return;
    const float* s = src + idx * 8;
    float4 v0 = *reinterpret_cast<const float4*>(s);
    float4 v1 = *reinterpret_cast<const float4*>(s + 4);
    float v[8] = {v0.x, v0.y, v0.z, v0.w, v1.x, v1.y, v1.z, v1.w};
    union { __nv_bfloat16 h[8]; uint4 u; } H, L;
    #pragma unroll
    for (int i = 0; i < 8; i++) {
        __nv_bfloat16 h = __float2bfloat16(v[i]);
        H.h[i] = h;
        L.h[i] = __float2bfloat16(v[i] - __bfloat162float(h));
    }
    *reinterpret_cast<uint4*>(hi + idx * 8) = H.u;
    *reinterpret_cast<uint4*>(lo + idx * 8) = L.u;
}

// ---------------------------------------------------------------------------
// Fused gate + causal depthwise conv(K=4) + gate; outputs split bf16 u.
//   gated[t,d] = Bg[t,d]*Xg[t,d];  u[t,d] = Cg[t,d]*sum_k gated[t-3+k,d]*w[d,k]
// ---------------------------------------------------------------------------
__global__ __launch_bounds__(256) void conv_gate_split(
    const float* __restrict__ bcx, const float* __restrict__ cw,
    __nv_bfloat16* __restrict__ uh, __nv_bfloat16* __restrict__ ul)
{
    size_t idx = (size_t)blockIdx.x * blockDim.x + threadIdx.x;
    if (idx >= (size_t)MTOK * 256) return;
    const int g = (int)(idx & 255);
    const size_t m = idx >> 8;
    const int d0 = g * 8;
    const int s = (int)(m % SEQ);

    float w[8][4];
    #pragma unroll
    for (int j = 0; j < 8; j++) {
        float4 wv = *reinterpret_cast<const float4*>(cw + (size_t)(d0 + j) * 4);
        w[j][0] = wv.x; w[j][1] = wv.y; w[j][2] = wv.z; w[j][3] = wv.w;
    }

    float acc[8] = {0, 0, 0, 0, 0, 0, 0, 0};
    #pragma unroll
    for (int back = 0; back < 4; back++) {
        if (s - back >= 0) {
            const float* row = bcx + (m - back) * (size_t)N1;
            float4 b0 = *reinterpret_cast<const float4*>(row + d0);
            float4 b1 = *reinterpret_cast<const float4*>(row + d0 + 4);
            float4 x0 = *reinterpret_cast<const float4*>(row + 2 * D_MODEL + d0);
            float4 x1 = *reinterpret_cast<const float4*>(row + 2 * D_MODEL + d0 + 4);
            float bb[8] = {b0.x, b0.y, b0.z, b0.w, b1.x, b1.y, b1.z, b1.w};
            float xx[8] = {x0.x, x0.y, x0.z, x0.w, x1.x, x1.y, x1.z, x1.w};
            #pragma unroll
            for (int j = 0; j < 8; j++)
                acc[j] = fmaf(bb[j] * xx[j], w[j][3 - back], acc[j]);
        }
    }
    const float* crow = bcx + m * (size_t)N1 + D_MODEL;
    float4 c0 = *reinterpret_cast<const float4*>(crow + d0);
    float4 c1 = *reinterpret_cast<const float4*>(crow + d0 + 4);
    float cc[8] = {c0.x, c0.y, c0.z, c0.w, c1.x, c1.y, c1.z, c1.w};

    union { __nv_bfloat16 h[8]; uint4 u; } H, L;
    #pragma unroll
    for (int j = 0; j < 8; j++) {
        float u = cc[j] * acc[j];
        __nv_bfloat16 h = __float2bfloat16(u);
        H.h[j] = h;
        L.h[j] = __float2bfloat16(u - __bfloat162float(h));
    }
    const size_t off = m * (size_t)D_MODEL + d0;
    *reinterpret_cast<uint4*>(uh + off) = H.u;
    *reinterpret_cast<uint4*>(ul + off) = L.u;
}

// ---------------------------------------------------------------------------
extern "C" void kernel_launch(void* const* d_in, const int* in_sizes, int n_in,
                              void* d_out, int out_size)
{
    const float* x  = (const float*)d_in[0];
    const float* w1 = (const float*)d_in[1];
    const float* w2 = (const float*)d_in[2];
    const float* cw = (const float*)d_in[3];
    float* out = (float*)d_out;

    __nv_bfloat16 *xh, *xl, *w1h, *w1l, *w2h, *w2l, *uh, *ul;
    float* bcx;
    cudaGetSymbolAddress((void**)&xh,  g_xh);
    cudaGetSymbolAddress((void**)&xl,  g_xl);
    cudaGetSymbolAddress((void**)&w1h, g_w1h);
    cudaGetSymbolAddress((void**)&w1l, g_w1l);
    cudaGetSymbolAddress((void**)&w2h, g_w2h);
    cudaGetSymbolAddress((void**)&w2l, g_w2l);
    cudaGetSymbolAddress((void**)&uh,  g_uh);
    cudaGetSymbolAddress((void**)&ul,  g_ul);
    cudaGetSymbolAddress((void**)&bcx, g_bcx);

    cudaFuncSetAttribute(gemm_split,
                         cudaFuncAttributeMaxDynamicSharedMemorySize, GEMM_SMEM);

    // splits
    split_bf16<<<(int)(((size_t)MTOK * KEL / 8 + 255) / 256), 256>>>(
        x, xh, xl, (size_t)MTOK * KEL / 8);
    split_bf16<<<(int)(((size_t)N1 * KEL / 8 + 255) / 256), 256>>>(
        w1, w1h, w1l, (size_t)N1 * KEL / 8);
    split_bf16<<<(int)(((size_t)D_MODEL * KEL / 8 + 255) / 256), 256>>>(
        w2, w2h, w2l, (size_t)D_MODEL * KEL / 8);

    // GEMM1: bcx = x @ w1^T
    {
        dim3 grid(N1 / 128, MTOK / 128);
        gemm_split<<<grid, 256, GEMM_SMEM>>>(xh, xl, w1h, w1l, bcx, N1);
    }

    // fused gate/conv/gate -> uh, ul
    conv_gate_split<<<MTOK * 256 / 256, 256>>>(bcx, cw, uh, ul);

    // GEMM2: out = u @ w2^T
    {
        dim3 grid(D_MODEL / 128, MTOK / 128);
        gemm_split<<<grid, 256, GEMM_SMEM>>>(uh, ul, w2h, w2l, out, D_MODEL);
    }
}

// round 4
// speedup vs baseline: 3.1001x; 1.2753x over previous
#include <cuda_runtime.h>
#include <cuda_bf16.h>
#include <cstdint>

// ---------------------------------------------------------------------------
// GatedShortBlock via split-bf16 HMMA (mma.sync):
//   bcx = x @ w1^T   (16384 x 6144, K=2048)
//   u   = Cg * causal_conv4(Bg * Xg)
//   out = u @ w2^T   (16384 x 2048, K=2048)
// C = Ah*Bh^T + Ah*Bl^T + Al*Bh^T  (bf16 operands, fp32 accum, err ~2^-17)
// R4: CTA tile 128x256, warp tile 64x64, K-slab 32, 4-stage cp.async pipeline.
// ---------------------------------------------------------------------------

#define D_MODEL 2048
#define SEQ     4096
#define MTOK    16384
#define N1      6144
#define KEL     2048
#define KT      64            // 2048 / 32 k-slabs
#define KSZ     4

// ---------------- scratch ----------------------------------------------------
__device__ __align__(16) __nv_bfloat16 g_xh [(size_t)MTOK * KEL];
__device__ __align__(16) __nv_bfloat16 g_xl [(size_t)MTOK * KEL];
__device__ __align__(16) __nv_bfloat16 g_w1h[(size_t)N1 * KEL];
__device__ __align__(16) __nv_bfloat16 g_w1l[(size_t)N1 * KEL];
__device__ __align__(16) __nv_bfloat16 g_w2h[(size_t)D_MODEL * KEL];
__device__ __align__(16) __nv_bfloat16 g_w2l[(size_t)D_MODEL * KEL];
__device__ __align__(16) __nv_bfloat16 g_uh [(size_t)MTOK * KEL];
__device__ __align__(16) __nv_bfloat16 g_ul [(size_t)MTOK * KEL];
__device__ float g_bcx[(size_t)MTOK * N1];

// ---------------- asm helpers ------------------------------------------------
__device__ __forceinline__ uint32_t smem_u32(const void* p) {
    uint32_t a;
    asm("{ .reg .u64 t; cvta.to.shared.u64 t, %1; cvt.u32.u64 %0, t; }" : "=r"(a) : "l"(p));
    return a;
}
__device__ __forceinline__ void cp16(uint32_t dst, const void* src) {
    asm volatile("cp.async.cg.shared.global [%0], [%1], 16;" :: "r"(dst), "l"(src));
}
#define CP_COMMIT() asm volatile("cp.async.commit_group;" ::: "memory")
#define CP_WAIT2()  asm volatile("cp.async.wait_group 2;" ::: "memory")

#define LDSM_X4(r0, r1, r2, r3, addr) \
    asm volatile("ldmatrix.sync.aligned.m8n8.x4.shared.b16 {%0,%1,%2,%3}, [%4];" \
        : "=r"(r0), "=r"(r1), "=r"(r2), "=r"(r3) : "r"(addr))

#define MMA16816(c, a0, a1, a2, a3, b0, b1) \
    asm volatile("mma.sync.aligned.m16n8k16.row.col.f32.bf16.bf16.f32 " \
        "{%0,%1,%2,%3}, {%4,%5,%6,%7}, {%8,%9}, {%0,%1,%2,%3};" \
        : "+f"((c)[0]), "+f"((c)[1]), "+f"((c)[2]), "+f"((c)[3]) \
        : "r"(a0), "r"(a1), "r"(a2), "r"(a3), "r"(b0), "r"(b1))

// ---------------------------------------------------------------------------
// GEMM kernel. Smem per stage (48KB): [Ah 8K | Al 8K | Bh 16K | Bl 16K],
// rows are 64B (32 K-elems), 16B chunks XOR-swizzled by ((row>>1)&3).
// ---------------------------------------------------------------------------
#define STAGE_B   49152
#define GEMM_SMEM (4 * STAGE_B)   // 196608

__global__ __launch_bounds__(256, 1) void gemm_split(
    const __nv_bfloat16* __restrict__ Ah, const __nv_bfloat16* __restrict__ Al,
    const __nv_bfloat16* __restrict__ Bh, const __nv_bfloat16* __restrict__ Bl,
    float* __restrict__ C, int Ntot)
{
    extern __shared__ __align__(1024) char smem[];
    const uint32_t sb = smem_u32(smem);
    const int tid  = threadIdx.x;
    const int lane = tid & 31;
    const int wid  = tid >> 5;
    const int wm   = wid >> 2;        // 0..1  (m)
    const int wn   = wid & 3;         // 0..3  (n)

    const size_t m0 = (size_t)blockIdx.y * 128;
    const size_t n0 = (size_t)blockIdx.x * 256;

    // ---- cp.async staging: rows of 64B, 4 chunks of 16B, swizzled ----------
    const char* pAh = (const char*)(Ah + m0 * (size_t)KEL);
    const char* pAl = (const char*)(Al + m0 * (size_t)KEL);
    const char* pBh = (const char*)(Bh + n0 * (size_t)KEL);
    const char* pBl = (const char*)(Bl + n0 * (size_t)KEL);

    auto load_stage = [&](int s, int kt) {
        const uint32_t st = sb + s * STAGE_B;
        const size_t kb = (size_t)kt * 64;   // byte offset along K
        #pragma unroll
        for (int rep = 0; rep < 2; rep++) {          // A: 128 rows x 4 chunks
            const int idx = rep * 256 + tid;
            const int row = idx >> 2, c = idx & 3;
            const uint32_t d = st + row * 64 + ((((uint32_t)c) ^ ((row >> 1) & 3)) << 4);
            const size_t so = (size_t)row * (KEL * 2) + kb + c * 16;
            cp16(d,        pAh + so);
            cp16(d + 8192, pAl + so);
        }
        #pragma unroll
        for (int rep = 0; rep < 4; rep++) {          // B: 256 rows x 4 chunks
            const int idx = rep * 256 + tid;
            const int row = idx >> 2, c = idx & 3;
            const uint32_t d = st + 16384 + row * 64 + ((((uint32_t)c) ^ ((row >> 1) & 3)) << 4);
            const size_t so = (size_t)row * (KEL * 2) + kb + c * 16;
            cp16(d,         pBh + so);
            cp16(d + 16384, pBl + so);
        }
    };

    load_stage(0, 0); CP_COMMIT();
    load_stage(1, 1); CP_COMMIT();
    load_stage(2, 2); CP_COMMIT();

    float acc[4][8][4];
    #pragma unroll
    for (int i = 0; i < 4; i++)
        #pragma unroll
        for (int j = 0; j < 8; j++)
            #pragma unroll
            for (int q = 0; q < 4; q++) acc[i][j][q] = 0.0f;

    // ldmatrix lane components
    const int lrow8  = lane & 7;
    const int lhalfA = (lane >> 3) & 1;
    const int lkA    = lane >> 4;
    const int lhalfB = lane >> 4;
    const int lkB    = (lane >> 3) & 1;

    for (int kt = 0; kt < KT; kt++) {
        CP_WAIT2();
        __syncthreads();
        if (kt + 3 < KT) load_stage((kt + 3) & 3, kt + 3);
        CP_COMMIT();

        const uint32_t st = sb + (kt & 3) * STAGE_B;
        #pragma unroll
        for (int ks = 0; ks < 2; ks++) {
            const int kc = ks * 2;
            uint32_t ahf[4][4], alf[4][4];
            #pragma unroll
            for (int i = 0; i < 4; i++) {
                const int row = wm * 64 + i * 16 + lrow8 + lhalfA * 8;
                const uint32_t ad = st + row * 64 +
                    ((((uint32_t)(kc + lkA)) ^ ((row >> 1) & 3)) << 4);
                LDSM_X4(ahf[i][0], ahf[i][1], ahf[i][2], ahf[i][3], ad);
                LDSM_X4(alf[i][0], alf[i][1], alf[i][2], alf[i][3], ad + 8192);
            }
            #pragma unroll
            for (int jp = 0; jp < 4; jp++) {
                const int nrow = wn * 64 + jp * 16 + lrow8 + lhalfB * 8;
                const uint32_t bd = st + 16384 + nrow * 64 +
                    ((((uint32_t)(kc + lkB)) ^ ((nrow >> 1) & 3)) << 4);
                uint32_t bh0, bh1, bh2, bh3, bl0, bl1, bl2, bl3;
                LDSM_X4(bh0, bh1, bh2, bh3, bd);
                LDSM_X4(bl0, bl1, bl2, bl3, bd + 16384);
                #pragma unroll
                for (int i = 0; i < 4; i++) {
                    float* c0 = acc[i][jp * 2];
                    float* c1 = acc[i][jp * 2 + 1];
                    MMA16816(c0, ahf[i][0], ahf[i][1], ahf[i][2], ahf[i][3], bh0, bh1);
                    MMA16816(c0, ahf[i][0], ahf[i][1], ahf[i][2], ahf[i][3], bl0, bl1);
                    MMA16816(c0, alf[i][0], alf[i][1], alf[i][2], alf[i][3], bh0, bh1);
                    MMA16816(c1, ahf[i][0], ahf[i][1], ahf[i][2], ahf[i][3], bh2, bh3);
                    MMA16816(c1, ahf[i][0], ahf[i][1], ahf[i][2], ahf[i][3], bl2, bl3);
                    MMA16816(c1, alf[i][0], alf[i][1], alf[i][2], alf[i][3], bh2, bh3);
                }
            }
        }
    }

    // ---- epilogue -----------------------------------------------------------
    #pragma unroll
    for (int i = 0; i < 4; i++) {
        const size_t r = m0 + wm * 64 + i * 16 + (lane >> 2);
        #pragma unroll
        for (int j = 0; j < 8; j++) {
            const size_t c = n0 + wn * 64 + j * 8 + (lane & 3) * 2;
            *reinterpret_cast<float2*>(C + r * (size_t)Ntot + c) =
                make_float2(acc[i][j][0], acc[i][j][1]);
            *reinterpret_cast<float2*>(C + (r + 8) * (size_t)Ntot + c) =
                make_float2(acc[i][j][2], acc[i][j][3]);
        }
    }
}

// ---------------------------------------------------------------------------
// fp32 -> (hi, lo) bf16 split, elementwise. 8 elements per thread.
// ---------------------------------------------------------------------------
__global__ __launch_bounds__(256) void split_bf16(
    const float* __restrict__ src, __nv_bfloat16* __restrict__ hi,
    __nv_bfloat16* __restrict__ lo, size_t total8)
{
    size_t idx = (size_t)blockIdx.x * blockDim.x + threadIdx.x;
    if (idx >= total8) return;
    const float* s = src + idx * 8;
    float4 v0 = *reinterpret_cast<const float4*>(s);
    float4 v1 = *reinterpret_cast<const float4*>(s + 4);
    float v[8] = {v0.x, v0.y, v0.z, v0.w, v1.x, v1.y, v1.z, v1.w};
    union { __nv_bfloat16 h[8]; uint4 u; } H, L;
    #pragma unroll
    for (int i = 0; i < 8; i++) {
        __nv_bfloat16 h = __float2bfloat16(v[i]);
        H.h[i] = h;
        L.h[i] = __float2bfloat16(v[i] - __bfloat162float(h));
    }
    *reinterpret_cast<uint4*>(hi + idx * 8) = H.u;
    *reinterpret_cast<uint4*>(lo + idx * 8) = L.u;
}

// ---------------------------------------------------------------------------
// Fused gate + causal depthwise conv(K=4) + gate; outputs split bf16 u.
// ---------------------------------------------------------------------------
__global__ __launch_bounds__(256) void conv_gate_split(
    const float* __restrict__ bcx, const float* __restrict__ cw,
    __nv_bfloat16* __restrict__ uh, __nv_bfloat16* __restrict__ ul)
{
    size_t idx = (size_t)blockIdx.x * blockDim.x + threadIdx.x;
    if (idx >= (size_t)MTOK * 256) return;
    const int g = (int)(idx & 255);
    const size_t m = idx >> 8;
    const int d0 = g * 8;
    const int s = (int)(m % SEQ);

    float w[8][4];
    #pragma unroll
    for (int j = 0; j < 8; j++) {
        float4 wv = *reinterpret_cast<const float4*>(cw + (size_t)(d0 + j) * 4);
        w[j][0] = wv.x; w[j][1] = wv.y; w[j][2] = wv.z; w[j][3] = wv.w;
    }

    float acc[8] = {0, 0, 0, 0, 0, 0, 0, 0};
    #pragma unroll
    for (int back = 0; back < 4; back++) {
        if (s - back >= 0) {
            const float* row = bcx + (m - back) * (size_t)N1;
            float4 b0 = *reinterpret_cast<const float4*>(row + d0);
            float4 b1 = *reinterpret_cast<const float4*>(row + d0 + 4);
            float4 x0 = *reinterpret_cast<const float4*>(row + 2 * D_MODEL + d0);
            float4 x1 = *reinterpret_cast<const float4*>(row + 2 * D_MODEL + d0 + 4);
            float bb[8] = {b0.x, b0.y, b0.z, b0.w, b1.x, b1.y, b1.z, b1.w};
            float xx[8] = {x0.x, x0.y, x0.z, x0.w, x1.x, x1.y, x1.z, x1.w};
            #pragma unroll
            for (int j = 0; j < 8; j++)
                acc[j] = fmaf(bb[j] * xx[j], w[j][3 - back], acc[j]);
        }
    }
    const float* crow = bcx + m * (size_t)N1 + D_MODEL;
    float4 c0 = *reinterpret_cast<const float4*>(crow + d0);
    float4 c1 = *reinterpret_cast<const float4*>(crow + d0 + 4);
    float cc[8] = {c0.x, c0.y, c0.z, c0.w, c1.x, c1.y, c1.z, c1.w};

    union { __nv_bfloat16 h[8]; uint4 u; } H, L;
    #pragma unroll
    for (int j = 0; j < 8; j++) {
        float u = cc[j] * acc[j];
        __nv_bfloat16 h = __float2bfloat16(u);
        H.h[j] = h;
        L.h[j] = __float2bfloat16(u - __bfloat162float(h));
    }
    const size_t off = m * (size_t)D_MODEL + d0;
    *reinterpret_cast<uint4*>(uh + off) = H.u;
    *reinterpret_cast<uint4*>(ul + off) = L.u;
}

// ---------------------------------------------------------------------------
extern "C" void kernel_launch(void* const* d_in, const int* in_sizes, int n_in,
                              void* d_out, int out_size)
{
    const float* x  = (const float*)d_in[0];
    const float* w1 = (const float*)d_in[1];
    const float* w2 = (const float*)d_in[2];
    const float* cw = (const float*)d_in[3];
    float* out = (float*)d_out;

    __nv_bfloat16 *xh, *xl, *w1h, *w1l, *w2h, *w2l, *uh, *ul;
    float* bcx;
    cudaGetSymbolAddress((void**)&xh,  g_xh);
    cudaGetSymbolAddress((void**)&xl,  g_xl);
    cudaGetSymbolAddress((void**)&w1h, g_w1h);
    cudaGetSymbolAddress((void**)&w1l, g_w1l);
    cudaGetSymbolAddress((void**)&w2h, g_w2h);
    cudaGetSymbolAddress((void**)&w2l, g_w2l);
    cudaGetSymbolAddress((void**)&uh,  g_uh);
    cudaGetSymbolAddress((void**)&ul,  g_ul);
    cudaGetSymbolAddress((void**)&bcx, g_bcx);

    cudaFuncSetAttribute(gemm_split,
                         cudaFuncAttributeMaxDynamicSharedMemorySize, GEMM_SMEM);

    split_bf16<<<(int)(((size_t)MTOK * KEL / 8 + 255) / 256), 256>>>(
        x, xh, xl, (size_t)MTOK * KEL / 8);
    split_bf16<<<(int)(((size_t)N1 * KEL / 8 + 255) / 256), 256>>>(
        w1, w1h, w1l, (size_t)N1 * KEL / 8);
    split_bf16<<<(int)(((size_t)D_MODEL * KEL / 8 + 255) / 256), 256>>>(
        w2, w2h, w2l, (size_t)D_MODEL * KEL / 8);

    // GEMM1: bcx = x @ w1^T
    {
        dim3 grid(N1 / 256, MTOK / 128);
        gemm_split<<<grid, 256, GEMM_SMEM>>>(xh, xl, w1h, w1l, bcx, N1);
    }

    conv_gate_split<<<MTOK * 256 / 256, 256>>>(bcx, cw, uh, ul);

    // GEMM2: out = u @ w2^T
    {
        dim3 grid(D_MODEL / 256, MTOK / 128);
        gemm_split<<<grid, 256, GEMM_SMEM>>>(uh, ul, w2h, w2l, out, D_MODEL);
    }
}